// round 14
// baseline (speedup 1.0000x reference)
#include <cuda_runtime.h>
#include <cuda_bf16.h>
#include <cuda_fp16.h>
#include <math.h>
#include <cstdint>
#include <cstring>

#define Bb   4
#define Ss   2048
#define Dd   1024
#define Hh   16
#define HDd  64
#define Mtot (Bb*Ss)            // 8192
#define NBH  (Bb*Hh*Ss*HDd)     // 8388608

// Scratch (__device__ globals; allocation-free rule)
__device__ __half        g_Q16[NBH], g_K16[NBH];           // Q,K fp16 head-split
__device__ __half        g_V16[NBH], g_Vt16[NBH];          // V fp16 (+transposed)
__device__ __half        g_C16[Bb*Ss*Dd];                  // ctx fp16
__device__ __nv_bfloat16 g_Wh[2u*1024*1024], g_Wl[2u*1024*1024]; // Wq,Wk planes
__device__ __half        g_Wv16[1024*1024], g_Wo16[1024*1024];
__device__ __nv_bfloat16 g_Ih[2u*Mtot*Dd], g_Il[2u*Mtot*Dd];     // query,key_t planes
__device__ __half        g_Iv16[(size_t)Mtot*Dd];          // value fp16
__device__ float g_Y[Bb*Ss*Dd];                 // out-proj raw (bias+resid in LN)
__device__ __half g_attn16[(size_t)Bb*Hh*Ss*Ss];           // unnorm probs fp16

// ---------------------------------------------------------------------------
__device__ __forceinline__ void bsplit(float x, __nv_bfloat16& h, __nv_bfloat16& l) {
    h = __float2bfloat16(x);
    l = __float2bfloat16(x - __bfloat162float(h));
}
__device__ __forceinline__ void split4_store(__nv_bfloat16* ph, __nv_bfloat16* pl, float4 v) {
    __nv_bfloat16 h0, h1, h2, h3, l0, l1, l2, l3;
    bsplit(v.x, h0, l0); bsplit(v.y, h1, l1);
    bsplit(v.z, h2, l2); bsplit(v.w, h3, l3);
    *(__nv_bfloat162*)(ph + 0) = __halves2bfloat162(h0, h1);
    *(__nv_bfloat162*)(ph + 2) = __halves2bfloat162(h2, h3);
    *(__nv_bfloat162*)(pl + 0) = __halves2bfloat162(l0, l1);
    *(__nv_bfloat162*)(pl + 2) = __halves2bfloat162(l2, l3);
}

// bf16 mma: D += A(16x16) * B(16x8), fp32 accum.
__device__ __forceinline__ void mma_bf16(float* c, const uint32_t* a,
                                         uint32_t b0, uint32_t b1) {
    asm volatile(
        "mma.sync.aligned.m16n8k16.row.col.f32.bf16.bf16.f32 "
        "{%0,%1,%2,%3}, {%4,%5,%6,%7}, {%8,%9}, {%0,%1,%2,%3};\n"
        : "+f"(c[0]), "+f"(c[1]), "+f"(c[2]), "+f"(c[3])
        : "r"(a[0]), "r"(a[1]), "r"(a[2]), "r"(a[3]), "r"(b0), "r"(b1));
}
// fp16 mma: D += A(16x16) * B(16x8), fp32 accum.
__device__ __forceinline__ void mma_f16(float* c, const uint32_t* a,
                                        uint32_t b0, uint32_t b1) {
    asm volatile(
        "mma.sync.aligned.m16n8k16.row.col.f32.f16.f16.f32 "
        "{%0,%1,%2,%3}, {%4,%5,%6,%7}, {%8,%9}, {%0,%1,%2,%3};\n"
        : "+f"(c[0]), "+f"(c[1]), "+f"(c[2]), "+f"(c[3])
        : "r"(a[0]), "r"(a[1]), "r"(a[2]), "r"(a[3]), "r"(b0), "r"(b1));
}

__device__ __forceinline__ void ldsm_x4(uint32_t* r, uint32_t addr) {
    asm volatile("ldmatrix.sync.aligned.m8n8.x4.shared.b16 {%0,%1,%2,%3}, [%4];\n"
                 : "=r"(r[0]), "=r"(r[1]), "=r"(r[2]), "=r"(r[3]) : "r"(addr));
}
__device__ __forceinline__ void ldsm_x2(uint32_t* r, uint32_t addr) {
    asm volatile("ldmatrix.sync.aligned.m8n8.x2.shared.b16 {%0,%1}, [%2];\n"
                 : "=r"(r[0]), "=r"(r[1]) : "r"(addr));
}
__device__ __forceinline__ void cp16(uint32_t daddr, const void* src) {
    asm volatile("cp.async.cg.shared.global [%0], [%1], 16;\n" :: "r"(daddr), "l"(src));
}

// ---------------------------------------------------------------------------
// Pre-split weights: Wq,Wk -> bf16 hi/lo; Wv,Wo -> fp16 single.
// ---------------------------------------------------------------------------
__global__ __launch_bounds__(256) void prep_w_kernel(
    const float* __restrict__ Wq, const float* __restrict__ Wk,
    const float* __restrict__ Wv, const float* __restrict__ Wo)
{
    int w = blockIdx.y;
    const float* W = (w == 0) ? Wq : (w == 1) ? Wk : (w == 2) ? Wv : Wo;
    size_t i = (size_t)blockIdx.x * 256 + threadIdx.x;   // float4 index
    float4 v = *(const float4*)(W + i * 4);
    if (w < 2) {
        __nv_bfloat16* dh = g_Wh + ((size_t)w << 20);
        __nv_bfloat16* dl = g_Wl + ((size_t)w << 20);
        split4_store(dh + i * 4, dl + i * 4, v);
    } else {
        __half* d = (w == 2) ? g_Wv16 : g_Wo16;
        *(__half2*)(d + i * 4)     = __floats2half2_rn(v.x, v.y);
        *(__half2*)(d + i * 4 + 2) = __floats2half2_rn(v.z, v.w);
    }
}

// Inputs: query,key_t -> bf16 hi/lo; value -> fp16 single.
__global__ __launch_bounds__(256) void prep_i_kernel(
    const float* __restrict__ q, const float* __restrict__ k,
    const float* __restrict__ v)
{
    int w = blockIdx.y;
    const float* X = (w == 0) ? q : (w == 1) ? k : v;
    size_t i = (size_t)blockIdx.x * 256 + threadIdx.x;
    float4 val = *(const float4*)(X + i * 4);
    if (w < 2) {
        __nv_bfloat16* dh = g_Ih + (size_t)w * Mtot * Dd;
        __nv_bfloat16* dl = g_Il + (size_t)w * Mtot * Dd;
        split4_store(dh + i * 4, dl + i * 4, val);
    } else {
        *(__half2*)(g_Iv16 + i * 4)     = __floats2half2_rn(val.x, val.y);
        *(__half2*)(g_Iv16 + i * 4 + 2) = __floats2half2_rn(val.z, val.w);
    }
}

// ---------------------------------------------------------------------------
// GEMM bf16x3 (Q+K projections in ONE launch, z selects). 256 threads,
// 8 warps of 64x32 tiles, 128x128 block tile, 2-stage cp.async, 2 CTAs/SM.
// z=0 -> g_Q16 (+bq, *0.125), z=1 -> g_K16 (+bk). fp16 outputs.
// ---------------------------------------------------------------------------
#define BM 128
#define BN 128
#define BK 32
#define KLD 40
#define G2STGE (4*128*KLD)              // elems per stage (4 planes)
#define G2SMEM (2*G2STGE*2)             // 81920 bytes

__global__ __launch_bounds__(256, 2) void gemm2_kernel(
    const float* __restrict__ bq, const float* __restrict__ bk)
{
    extern __shared__ __align__(16) char sm[];
    uint32_t smb = (uint32_t)__cvta_generic_to_shared(sm);

    int sel = blockIdx.z;
    const float* bias = sel ? bk : bq;
    const __nv_bfloat16* Ah = g_Ih + (size_t)sel * Mtot * Dd;
    const __nv_bfloat16* Al = g_Il + (size_t)sel * Mtot * Dd;
    const __nv_bfloat16* Wh_ = g_Wh + ((size_t)sel << 20);
    const __nv_bfloat16* Wl_ = g_Wl + ((size_t)sel << 20);

    int t = threadIdx.x;
    int lane = t & 31, wid = t >> 5;
    int g = lane >> 2, qi = lane & 3;
    int wm = wid & 1;            // 0..1 -> 64-row strip
    int wn = wid >> 1;           // 0..3 -> 32-col strip
    int m0 = blockIdx.y * BM, n0 = blockIdx.x * BN;

    float c[4][4][4];
    #pragma unroll
    for (int mi = 0; mi < 4; mi++)
        #pragma unroll
        for (int ni = 0; ni < 4; ni++)
            #pragma unroll
            for (int x = 0; x < 4; x++) c[mi][ni][x] = 0.f;

    auto issue = [&](int k0, int st) {
        #pragma unroll
        for (int i = 0; i < 8; i++) {
            int id = t + i * 256;            // 0..2047
            int p = id >> 9;
            int r = (id >> 2) & 127;
            int c8 = (id & 3) << 3;
            uint32_t d = smb + (uint32_t)(st * G2STGE + p * 128 * KLD + r * KLD + c8) * 2;
            const __nv_bfloat16* src;
            if (p == 0)      src = Ah  + (size_t)(m0 + r) * Dd + k0 + c8;
            else if (p == 1) src = Al  + (size_t)(m0 + r) * Dd + k0 + c8;
            else if (p == 2) src = Wh_ + (size_t)(n0 + r) * Dd + k0 + c8;
            else             src = Wl_ + (size_t)(n0 + r) * Dd + k0 + c8;
            cp16(d, src);
        }
    };

    int arow = (lane & 7) + ((lane >> 3) & 1) * 8;
    int acol = ((lane >> 4) & 1) * 8;
    int bl_ = lane & 15;
    int brow = bl_ & 7;
    int bcol = ((bl_ >> 3) & 1) * 8;

    issue(0, 0);
    asm volatile("cp.async.commit_group;\n");

    const int NKT = Dd / BK;   // 32
    for (int kt = 0; kt < NKT; kt++) {
        if (kt + 1 < NKT) issue((kt + 1) * BK, (kt + 1) & 1);
        asm volatile("cp.async.commit_group;\n");
        asm volatile("cp.async.wait_group 1;\n");
        __syncthreads();

        uint32_t sb = smb + (uint32_t)((kt & 1) * G2STGE) * 2;
        uint32_t pAh = sb;
        uint32_t pAl = sb + 128 * KLD * 2;
        uint32_t pBh = sb + 2 * 128 * KLD * 2;
        uint32_t pBl = sb + 3 * 128 * KLD * 2;

        #pragma unroll
        for (int ks = 0; ks < 2; ks++) {
            uint32_t ah[4][4], al2[4][4], bh[4][2], bl2[4][2];
            #pragma unroll
            for (int mi = 0; mi < 4; mi++) {
                uint32_t off = (uint32_t)((wm * 64 + mi * 16 + arow) * KLD
                                          + ks * 16 + acol) * 2;
                ldsm_x4(ah[mi], pAh + off);
                ldsm_x4(al2[mi], pAl + off);
            }
            #pragma unroll
            for (int ni = 0; ni < 4; ni++) {
                uint32_t off = (uint32_t)((wn * 32 + ni * 8 + brow) * KLD
                                          + ks * 16 + bcol) * 2;
                ldsm_x2(bh[ni], pBh + off);
                ldsm_x2(bl2[ni], pBl + off);
            }
            #pragma unroll
            for (int mi = 0; mi < 4; mi++)
                #pragma unroll
                for (int ni = 0; ni < 4; ni++) {
                    mma_bf16(c[mi][ni], ah[mi], bh[ni][0], bh[ni][1]);
                    mma_bf16(c[mi][ni], ah[mi], bl2[ni][0], bl2[ni][1]);
                    mma_bf16(c[mi][ni], al2[mi], bh[ni][0], bh[ni][1]);
                }
        }
        __syncthreads();   // protect stage kt before it is re-issued (kt+2)
    }

    __half* D = sel ? g_K16 : g_Q16;
    float scale = sel ? 1.0f : 0.125f;

    #pragma unroll
    for (int mi = 0; mi < 4; mi++) {
        int R0 = m0 + wm * 64 + mi * 16 + g;
        int bb = R0 >> 11, srow = R0 & 2047;
        #pragma unroll
        for (int ni = 0; ni < 4; ni++) {
            int C0 = n0 + wn * 32 + ni * 8 + 2 * qi;
            int hh = C0 >> 6, d = C0 & 63;
            float2 b2 = *(const float2*)(bias + C0);
            size_t off0 = (((size_t)(bb * Hh + hh)) * Ss + srow) * HDd + d;
            *(__half2*)(D + off0) =
                __floats2half2_rn((c[mi][ni][0] + b2.x) * scale,
                                  (c[mi][ni][1] + b2.y) * scale);
            *(__half2*)(D + off0 + 512) =
                __floats2half2_rn((c[mi][ni][2] + b2.x) * scale,
                                  (c[mi][ni][3] + b2.y) * scale);
        }
    }
}

// ---------------------------------------------------------------------------
// GEMM fp16 single-pass (V projection, out projection). 256 threads,
// 8 warps of 64x32 tiles, 2-stage cp.async.
// dst 2 -> V head-split fp16 (+bias). dst 3 -> fp32 g_Y.
// ---------------------------------------------------------------------------
#define GFSTGE (2*128*KLD)              // elems per stage (2 planes)
#define GFSMEM (2*GFSTGE*2)             // 40960 bytes

__global__ __launch_bounds__(256, 2) void gemm_f16_kernel(
    int asel, const float* __restrict__ bias, int dst)
{
    extern __shared__ __align__(16) char sm[];
    uint32_t smb = (uint32_t)__cvta_generic_to_shared(sm);

    const __half* A = (asel == 2) ? g_Iv16 : g_C16;
    const __half* W = (asel == 2) ? g_Wv16 : g_Wo16;

    int t = threadIdx.x;
    int lane = t & 31, wid = t >> 5;
    int g = lane >> 2, qi = lane & 3;
    int wm = wid & 1;
    int wn = wid >> 1;
    int m0 = blockIdx.y * BM, n0 = blockIdx.x * BN;

    float c[4][4][4];
    #pragma unroll
    for (int mi = 0; mi < 4; mi++)
        #pragma unroll
        for (int ni = 0; ni < 4; ni++)
            #pragma unroll
            for (int x = 0; x < 4; x++) c[mi][ni][x] = 0.f;

    auto issue = [&](int k0, int st) {
        #pragma unroll
        for (int i = 0; i < 4; i++) {
            int id = t + i * 256;            // 0..1023
            int p = id >> 9;                 // 0=A, 1=W
            int q = id & 511;
            int r = q >> 2;
            int c8 = (q & 3) << 3;
            uint32_t d = smb + (uint32_t)(st * GFSTGE + p * 128 * KLD + r * KLD + c8) * 2;
            const __half* src = (p == 0) ? (A + (size_t)(m0 + r) * Dd + k0 + c8)
                                         : (W + (size_t)(n0 + r) * Dd + k0 + c8);
            cp16(d, src);
        }
    };

    int arow = (lane & 7) + ((lane >> 3) & 1) * 8;
    int acol = ((lane >> 4) & 1) * 8;
    int bl_ = lane & 15;
    int brow = bl_ & 7;
    int bcol = ((bl_ >> 3) & 1) * 8;

    issue(0, 0);
    asm volatile("cp.async.commit_group;\n");

    const int NKT = Dd / BK;
    for (int kt = 0; kt < NKT; kt++) {
        if (kt + 1 < NKT) issue((kt + 1) * BK, (kt + 1) & 1);
        asm volatile("cp.async.commit_group;\n");
        asm volatile("cp.async.wait_group 1;\n");
        __syncthreads();

        uint32_t sb = smb + (uint32_t)((kt & 1) * GFSTGE) * 2;
        uint32_t pA = sb;
        uint32_t pB = sb + 128 * KLD * 2;

        #pragma unroll
        for (int ks = 0; ks < 2; ks++) {
            uint32_t a[4][4], b[4][2];
            #pragma unroll
            for (int mi = 0; mi < 4; mi++) {
                uint32_t off = (uint32_t)((wm * 64 + mi * 16 + arow) * KLD
                                          + ks * 16 + acol) * 2;
                ldsm_x4(a[mi], pA + off);
            }
            #pragma unroll
            for (int ni = 0; ni < 4; ni++) {
                uint32_t off = (uint32_t)((wn * 32 + ni * 8 + brow) * KLD
                                          + ks * 16 + bcol) * 2;
                ldsm_x2(b[ni], pB + off);
            }
            #pragma unroll
            for (int mi = 0; mi < 4; mi++)
                #pragma unroll
                for (int ni = 0; ni < 4; ni++)
                    mma_f16(c[mi][ni], a[mi], b[ni][0], b[ni][1]);
        }
        __syncthreads();
    }

    if (dst == 3) {
        #pragma unroll
        for (int mi = 0; mi < 4; mi++) {
            int R0 = m0 + wm * 64 + mi * 16 + g;
            #pragma unroll
            for (int ni = 0; ni < 4; ni++) {
                int C0 = n0 + wn * 32 + ni * 8 + 2 * qi;
                *(float2*)(g_Y + (size_t)R0 * Dd + C0) =
                    make_float2(c[mi][ni][0], c[mi][ni][1]);
                *(float2*)(g_Y + (size_t)(R0 + 8) * Dd + C0) =
                    make_float2(c[mi][ni][2], c[mi][ni][3]);
            }
        }
        return;
    }

    // dst == 2: V head-split fp16 (+bias)
    #pragma unroll
    for (int mi = 0; mi < 4; mi++) {
        int R0 = m0 + wm * 64 + mi * 16 + g;
        int bb = R0 >> 11, srow = R0 & 2047;
        #pragma unroll
        for (int ni = 0; ni < 4; ni++) {
            int C0 = n0 + wn * 32 + ni * 8 + 2 * qi;
            int hh = C0 >> 6, d = C0 & 63;
            float2 b2 = *(const float2*)(bias + C0);
            size_t off0 = (((size_t)(bb * Hh + hh)) * Ss + srow) * HDd + d;
            *(__half2*)(g_V16 + off0) =
                __floats2half2_rn(c[mi][ni][0] + b2.x, c[mi][ni][1] + b2.y);
            *(__half2*)(g_V16 + off0 + 512) =
                __floats2half2_rn(c[mi][ni][2] + b2.x, c[mi][ni][3] + b2.y);
        }
    }
}

// ---------------------------------------------------------------------------
// Transpose V per (b,h): [s][d] -> [d][s] (fp16 single plane).
// ---------------------------------------------------------------------------
__global__ __launch_bounds__(256) void vtrans_kernel()
{
    __shared__ __half sT[64 * 72];
    int t = threadIdx.x;
    int bh = blockIdx.y;
    int s0 = blockIdx.x * 64;
    const __half* V = g_V16 + (size_t)bh * (Ss * HDd);

    #pragma unroll
    for (int i = 0; i < 2; i++) {
        int idx = t + i * 256;
        int row = idx >> 3, c8 = (idx & 7) << 3;
        *(float4*)&sT[row * 72 + c8] = *(const float4*)&V[(size_t)(s0 + row) * HDd + c8];
    }
    __syncthreads();

    #pragma unroll
    for (int i = 0; i < 2; i++) {
        int idx = t + i * 256;
        int d = idx & 63, s8 = (idx >> 6) << 3;
        uint32_t outv[4];
        #pragma unroll
        for (int k = 0; k < 4; k++) {
            __half2 hh;
            hh.x = sT[(s8 + 2 * k) * 72 + d];
            hh.y = sT[(s8 + 2 * k + 1) * 72 + d];
            outv[k] = *(uint32_t*)&hh;
        }
        *(float4*)&g_Vt16[((size_t)bh * HDd + d) * Ss + s0 + s8] = *(float4*)outv;
    }
}

// ---------------------------------------------------------------------------
// Attention: QK^T fp16x1, exp in regs, unnorm probs -> fp16 scratch (L2-warm),
// PV fp16x1, tail reads fp16 scratch and writes normalized fp32 to output.
// smem: 2 stages x 2 planes x 64x72 fp16 = 36864 B. 2 CTAs/SM.
// ---------------------------------------------------------------------------
#define APL   (64*72*2)
#define ASTGB (2*APL)
#define ATTN_SMEM (2*ASTGB)     // 36864

__global__ __launch_bounds__(256, 2) void attn_mma_kernel(float* __restrict__ attn_ext,
                                                          int write_out)
{
    extern __shared__ __align__(16) char dynsm[];
    uint32_t smb = (uint32_t)__cvta_generic_to_shared(dynsm);

    int t = threadIdx.x;
    int lane = t & 31, w = t >> 5;
    int g = lane >> 2, qi = lane & 3;
    int bh = blockIdx.y, q0 = blockIdx.x * 128;
    int b = bh >> 4, h = bh & 15;

    const __half* Qp = g_Q16  + (size_t)bh * (Ss * HDd);
    const __half* Kp = g_K16  + (size_t)bh * (Ss * HDd);
    const __half* Vt = g_Vt16 + (size_t)bh * (Ss * HDd);

    int qrow = q0 + w * 16 + g;

    // Q A-fragments in registers (fp16; Q pre-scaled by 0.125)
    uint32_t qf[4][4];
    #pragma unroll
    for (int kk = 0; kk < 4; kk++) {
        int c0 = kk * 16 + 2 * qi;
        qf[kk][0] = *(const uint32_t*)&Qp[(size_t)qrow * HDd + c0];
        qf[kk][1] = *(const uint32_t*)&Qp[(size_t)(qrow + 8) * HDd + c0];
        qf[kk][2] = *(const uint32_t*)&Qp[(size_t)qrow * HDd + c0 + 8];
        qf[kk][3] = *(const uint32_t*)&Qp[(size_t)(qrow + 8) * HDd + c0 + 8];
    }

    float o[8][4];
    #pragma unroll
    for (int j = 0; j < 8; j++)
        #pragma unroll
        for (int x = 0; x < 4; x++) o[j][x] = 0.f;
    float rs0 = 0.f, rs1 = 0.f;

    auto issue_stage = [&](int kt, int st) {
        #pragma unroll
        for (int i = 0; i < 2; i++) {
            int idx = t + i * 256;
            int row = idx >> 3, c8 = (idx & 7) << 3;
            uint32_t doff = smb + st * ASTGB + (row * 72 + c8) * 2;
            cp16(doff,       &Kp[(size_t)(kt * 64 + row) * HDd + c8]);
            cp16(doff + APL, &Vt[(size_t)row * Ss + kt * 64 + c8]);
        }
    };

    issue_stage(0, 0);
    asm volatile("cp.async.commit_group;\n");

    for (int kt = 0; kt < Ss / 64; kt++) {
        if (kt + 1 < Ss / 64) issue_stage(kt + 1, (kt + 1) & 1);
        asm volatile("cp.async.commit_group;\n");
        asm volatile("cp.async.wait_group 1;\n");
        __syncthreads();

        const __half* sK = (const __half*)(dynsm + (kt & 1) * ASTGB);
        const __half* sV = sK + 64 * 72;

        uint32_t pfh[4][4];

        #pragma unroll
        for (int j = 0; j < 8; j++) {
            float s[4] = {0.f, 0.f, 0.f, 0.f};
            #pragma unroll
            for (int kk = 0; kk < 4; kk++) {
                const __half* kb = &sK[(j * 8 + g) * 72 + kk * 16 + 2 * qi];
                uint32_t b0 = *(const uint32_t*)kb;
                uint32_t b1 = *(const uint32_t*)(kb + 8);
                mma_f16(s, qf[kk], b0, b1);
            }
            float p0 = __expf(s[0]), p1 = __expf(s[1]);
            float p2 = __expf(s[2]), p3 = __expf(s[3]);
            rs0 += p0 + p1;
            rs1 += p2 + p3;

            int kk2 = j >> 1, rb = (j & 1) << 1;
            __half2 h01 = __floats2half2_rn(p0, p1);
            __half2 h23 = __floats2half2_rn(p2, p3);
            pfh[kk2][rb]     = *(uint32_t*)&h01;
            pfh[kk2][rb + 1] = *(uint32_t*)&h23;

            // fp16 unnormalized probs to scratch (exact values used by PV)
            size_t coff = (size_t)kt * 64 + j * 8 + 2 * qi;
            *(uint32_t*)&g_attn16[((size_t)bh * Ss + qrow) * Ss + coff]     = pfh[kk2][rb];
            *(uint32_t*)&g_attn16[((size_t)bh * Ss + qrow + 8) * Ss + coff] = pfh[kk2][rb + 1];
        }

        #pragma unroll
        for (int j = 0; j < 8; j++) {
            #pragma unroll
            for (int kk = 0; kk < 4; kk++) {
                const __half* vb = &sV[(j * 8 + g) * 72 + kk * 16 + 2 * qi];
                uint32_t b0 = *(const uint32_t*)vb;
                uint32_t b1 = *(const uint32_t*)(vb + 8);
                mma_f16(o[j], pfh[kk], b0, b1);
            }
        }
        __syncthreads();
    }

    rs0 += __shfl_xor_sync(0xffffffffu, rs0, 1);
    rs0 += __shfl_xor_sync(0xffffffffu, rs0, 2);
    rs1 += __shfl_xor_sync(0xffffffffu, rs1, 1);
    rs1 += __shfl_xor_sync(0xffffffffu, rs1, 2);
    float il0 = 1.f / rs0, il1 = 1.f / rs1;

    // ctx out (normalized) as fp16
    #pragma unroll
    for (int j = 0; j < 8; j++) {
        float v0 = o[j][0] * il0, v1 = o[j][1] * il0;
        float v2 = o[j][2] * il1, v3 = o[j][3] * il1;
        size_t off0 = ((size_t)(b * Ss) + qrow) * Dd + h * HDd + j * 8 + 2 * qi;
        size_t off1 = off0 + (size_t)8 * Dd;
        *(__half2*)&g_C16[off0] = __floats2half2_rn(v0, v1);
        *(__half2*)&g_C16[off1] = __floats2half2_rn(v2, v3);
    }

    // Tail: read fp16 scratch (L2-warm, 0.5MB/CTA), write normalized fp32 out.
    if (write_out) {
        float* sInvl = (float*)dynsm;
        __syncthreads();            // scratch writes visible; smem reuse safe
        if (qi == 0) {
            sInvl[w * 16 + g]     = il0;
            sInvl[w * 16 + g + 8] = il1;
        }
        __syncthreads();
        const __half* sb = g_attn16 + ((size_t)bh * Ss + q0) * Ss;
        float* ob = attn_ext + ((size_t)bh * Ss + q0) * Ss;
        for (int r = 0; r < 128; r++) {
            float il = sInvl[r];
            uint4 hv = *(const uint4*)(sb + (size_t)r * Ss + (t << 3));
            const __half2* hp = (const __half2*)&hv;
            float2 f0 = __half22float2(hp[0]);
            float2 f1 = __half22float2(hp[1]);
            float2 f2 = __half22float2(hp[2]);
            float2 f3 = __half22float2(hp[3]);
            float4 o1 = make_float4(f0.x * il, f0.y * il, f1.x * il, f1.y * il);
            float4 o2 = make_float4(f2.x * il, f2.y * il, f3.x * il, f3.y * il);
            *(float4*)(ob + (size_t)r * Ss + (t << 3))     = o1;
            *(float4*)(ob + (size_t)r * Ss + (t << 3) + 4) = o2;
        }
    }
}

// ---------------------------------------------------------------------------
// LayerNorm over D=1024 per row; fuses out-proj bias + residual(query).
// ---------------------------------------------------------------------------
__global__ __launch_bounds__(256) void ln_kernel(const float* __restrict__ gamma,
                                                 const float* __restrict__ beta,
                                                 const float* __restrict__ bo,
                                                 const float* __restrict__ query,
                                                 float* __restrict__ outext,
                                                 int use_internal)
{
    float* out = use_internal ? g_Y : outext;
    int row = blockIdx.x;
    const float* y = g_Y + (size_t)row * Dd;
    const float* q = query + (size_t)row * Dd;
    int t = threadIdx.x;
    int lane = t & 31, warp = t >> 5;
    __shared__ float red[8];

    int c = t << 2;
    float4 x  = *(const float4*)(y + c);
    float4 qv = *(const float4*)(q + c);
    float4 bv = *(const float4*)(bo + c);
    x.x += qv.x + bv.x; x.y += qv.y + bv.y;
    x.z += qv.z + bv.z; x.w += qv.w + bv.w;

    float sum = x.x + x.y + x.z + x.w;
    #pragma unroll
    for (int o = 16; o > 0; o >>= 1) sum += __shfl_xor_sync(0xffffffffu, sum, o);
    if (lane == 0) red[warp] = sum;
    __syncthreads();
    float tot = 0.f;
    #pragma unroll
    for (int w = 0; w < 8; w++) tot += red[w];
    float mean = tot * (1.f / Dd);

    float dx[4] = {x.x - mean, x.y - mean, x.z - mean, x.w - mean};
    float vs = dx[0]*dx[0] + dx[1]*dx[1] + dx[2]*dx[2] + dx[3]*dx[3];
    #pragma unroll
    for (int o = 16; o > 0; o >>= 1) vs += __shfl_xor_sync(0xffffffffu, vs, o);
    __syncthreads();
    if (lane == 0) red[warp] = vs;
    __syncthreads();
    float vtot = 0.f;
    #pragma unroll
    for (int w = 0; w < 8; w++) vtot += red[w];
    float r = rsqrtf(vtot * (1.f / Dd) + 1e-5f);

    float4 o4;
    o4.x = dx[0] * r * gamma[c + 0] + beta[c + 0];
    o4.y = dx[1] * r * gamma[c + 1] + beta[c + 1];
    o4.z = dx[2] * r * gamma[c + 2] + beta[c + 2];
    o4.w = dx[3] * r * gamma[c + 3] + beta[c + 3];
    *(float4*)(out + (size_t)row * Dd + c) = o4;
}

// ---------------------------------------------------------------------------
extern "C" void kernel_launch(void* const* d_in, const int* in_sizes, int n_in,
                              void* d_out, int out_size)
{
    const float* query = (const float*)d_in[0];
    const float* key_t = (const float*)d_in[1];
    const float* value = (const float*)d_in[2];
    const float* Wq    = (const float*)d_in[3];
    const float* bq    = (const float*)d_in[4];
    const float* Wk    = (const float*)d_in[5];
    const float* bk    = (const float*)d_in[6];
    const float* Wv    = (const float*)d_in[7];
    const float* bv    = (const float*)d_in[8];
    const float* Wo    = (const float*)d_in[9];
    const float* bo    = (const float*)d_in[10];
    const float* gamma = (const float*)d_in[11];
    const float* beta  = (const float*)d_in[12];

    float* out = (float*)d_out;
    const long long BSD = (long long)Bb * Ss * Dd;
    const long long ATT = (long long)Bb * Hh * Ss * (long long)Ss;

    float* attn_ext = out;
    int write_out = 0;
    float* out_ext = out;
    int out_internal = 0;
    if ((long long)out_size >= BSD + ATT) {
        attn_ext = out + BSD;
        write_out = 1;
    } else if ((long long)out_size == ATT) {
        attn_ext = out;
        write_out = 1;
        out_internal = 1;
    }

    cudaFuncSetAttribute(attn_mma_kernel,
                         cudaFuncAttributeMaxDynamicSharedMemorySize, ATTN_SMEM);
    cudaFuncSetAttribute(gemm2_kernel,
                         cudaFuncAttributeMaxDynamicSharedMemorySize, G2SMEM);
    cudaFuncSetAttribute(gemm_f16_kernel,
                         cudaFuncAttributeMaxDynamicSharedMemorySize, GFSMEM);

    prep_w_kernel<<<dim3(1024, 4), 256>>>(Wq, Wk, Wv, Wo);
    prep_i_kernel<<<dim3(8192, 3), 256>>>(query, key_t, value);

    dim3 ggrid(Dd / BN, Mtot / BM);         // (8, 64)
    dim3 ggrid2(Dd / BN, Mtot / BM, 2);     // Q+K fused
    gemm2_kernel<<<ggrid2, 256, G2SMEM>>>(bq, bk);
    gemm_f16_kernel<<<ggrid, 256, GFSMEM>>>(2, bv, 2);

    vtrans_kernel<<<dim3(Ss / 64, Bb * Hh), 256>>>();

    attn_mma_kernel<<<dim3(Ss / 128, Bb * Hh), 256, ATTN_SMEM>>>(attn_ext, write_out);

    gemm_f16_kernel<<<ggrid, 256, GFSMEM>>>(3, nullptr, 3);

    ln_kernel<<<Mtot, 256>>>(gamma, beta, bo, query, out_ext, out_internal);
}

// round 15
// speedup vs baseline: 1.0867x; 1.0867x over previous
#include <cuda_runtime.h>
#include <cuda_bf16.h>
#include <cuda_fp16.h>
#include <math.h>
#include <cstdint>
#include <cstring>

#define Bb   4
#define Ss   2048
#define Dd   1024
#define Hh   16
#define HDd  64
#define Mtot (Bb*Ss)            // 8192
#define NBH  (Bb*Hh*Ss*HDd)     // 8388608

// Scratch (__device__ globals; allocation-free rule)
__device__ __half        g_Q16[NBH], g_K16[NBH];           // Q,K fp16 head-split
__device__ __half        g_V16[NBH], g_Vt16[NBH];          // V fp16 (+transposed)
__device__ __half        g_C16[Bb*Ss*Dd];                  // ctx fp16
__device__ __nv_bfloat16 g_Wh[2u*1024*1024], g_Wl[2u*1024*1024]; // Wq,Wk planes
__device__ __half        g_Wv16[1024*1024], g_Wo16[1024*1024];
__device__ __nv_bfloat16 g_Ih[2u*Mtot*Dd], g_Il[2u*Mtot*Dd];     // query,key_t planes
__device__ __half        g_Iv16[(size_t)Mtot*Dd];          // value fp16
__device__ float g_Y[Bb*Ss*Dd];                 // out-proj raw (bias+resid in LN)
__device__ float g_attn_scratch[(size_t)Bb*Hh*Ss*Ss];

// ---------------------------------------------------------------------------
__device__ __forceinline__ void bsplit(float x, __nv_bfloat16& h, __nv_bfloat16& l) {
    h = __float2bfloat16(x);
    l = __float2bfloat16(x - __bfloat162float(h));
}
__device__ __forceinline__ void split4_store(__nv_bfloat16* ph, __nv_bfloat16* pl, float4 v) {
    __nv_bfloat16 h0, h1, h2, h3, l0, l1, l2, l3;
    bsplit(v.x, h0, l0); bsplit(v.y, h1, l1);
    bsplit(v.z, h2, l2); bsplit(v.w, h3, l3);
    *(__nv_bfloat162*)(ph + 0) = __halves2bfloat162(h0, h1);
    *(__nv_bfloat162*)(ph + 2) = __halves2bfloat162(h2, h3);
    *(__nv_bfloat162*)(pl + 0) = __halves2bfloat162(l0, l1);
    *(__nv_bfloat162*)(pl + 2) = __halves2bfloat162(l2, l3);
}

// bf16 mma: D += A(16x16) * B(16x8), fp32 accum.
__device__ __forceinline__ void mma_bf16(float* c, const uint32_t* a,
                                         uint32_t b0, uint32_t b1) {
    asm volatile(
        "mma.sync.aligned.m16n8k16.row.col.f32.bf16.bf16.f32 "
        "{%0,%1,%2,%3}, {%4,%5,%6,%7}, {%8,%9}, {%0,%1,%2,%3};\n"
        : "+f"(c[0]), "+f"(c[1]), "+f"(c[2]), "+f"(c[3])
        : "r"(a[0]), "r"(a[1]), "r"(a[2]), "r"(a[3]), "r"(b0), "r"(b1));
}
// fp16 mma: D += A(16x16) * B(16x8), fp32 accum.
__device__ __forceinline__ void mma_f16(float* c, const uint32_t* a,
                                        uint32_t b0, uint32_t b1) {
    asm volatile(
        "mma.sync.aligned.m16n8k16.row.col.f32.f16.f16.f32 "
        "{%0,%1,%2,%3}, {%4,%5,%6,%7}, {%8,%9}, {%0,%1,%2,%3};\n"
        : "+f"(c[0]), "+f"(c[1]), "+f"(c[2]), "+f"(c[3])
        : "r"(a[0]), "r"(a[1]), "r"(a[2]), "r"(a[3]), "r"(b0), "r"(b1));
}

__device__ __forceinline__ void ldsm_x4(uint32_t* r, uint32_t addr) {
    asm volatile("ldmatrix.sync.aligned.m8n8.x4.shared.b16 {%0,%1,%2,%3}, [%4];\n"
                 : "=r"(r[0]), "=r"(r[1]), "=r"(r[2]), "=r"(r[3]) : "r"(addr));
}
__device__ __forceinline__ void ldsm_x2(uint32_t* r, uint32_t addr) {
    asm volatile("ldmatrix.sync.aligned.m8n8.x2.shared.b16 {%0,%1}, [%2];\n"
                 : "=r"(r[0]), "=r"(r[1]) : "r"(addr));
}
__device__ __forceinline__ void cp16(uint32_t daddr, const void* src) {
    asm volatile("cp.async.cg.shared.global [%0], [%1], 16;\n" :: "r"(daddr), "l"(src));
}

// ---------------------------------------------------------------------------
// Pre-split weights: Wq,Wk -> bf16 hi/lo; Wv,Wo -> fp16 single.
// ---------------------------------------------------------------------------
__global__ __launch_bounds__(256) void prep_w_kernel(
    const float* __restrict__ Wq, const float* __restrict__ Wk,
    const float* __restrict__ Wv, const float* __restrict__ Wo)
{
    int w = blockIdx.y;
    const float* W = (w == 0) ? Wq : (w == 1) ? Wk : (w == 2) ? Wv : Wo;
    size_t i = (size_t)blockIdx.x * 256 + threadIdx.x;   // float4 index
    float4 v = *(const float4*)(W + i * 4);
    if (w < 2) {
        __nv_bfloat16* dh = g_Wh + ((size_t)w << 20);
        __nv_bfloat16* dl = g_Wl + ((size_t)w << 20);
        split4_store(dh + i * 4, dl + i * 4, v);
    } else {
        __half* d = (w == 2) ? g_Wv16 : g_Wo16;
        *(__half2*)(d + i * 4)     = __floats2half2_rn(v.x, v.y);
        *(__half2*)(d + i * 4 + 2) = __floats2half2_rn(v.z, v.w);
    }
}

// Inputs: query,key_t -> bf16 hi/lo; value -> fp16 single.
__global__ __launch_bounds__(256) void prep_i_kernel(
    const float* __restrict__ q, const float* __restrict__ k,
    const float* __restrict__ v)
{
    int w = blockIdx.y;
    const float* X = (w == 0) ? q : (w == 1) ? k : v;
    size_t i = (size_t)blockIdx.x * 256 + threadIdx.x;
    float4 val = *(const float4*)(X + i * 4);
    if (w < 2) {
        __nv_bfloat16* dh = g_Ih + (size_t)w * Mtot * Dd;
        __nv_bfloat16* dl = g_Il + (size_t)w * Mtot * Dd;
        split4_store(dh + i * 4, dl + i * 4, val);
    } else {
        *(__half2*)(g_Iv16 + i * 4)     = __floats2half2_rn(val.x, val.y);
        *(__half2*)(g_Iv16 + i * 4 + 2) = __floats2half2_rn(val.z, val.w);
    }
}

// ---------------------------------------------------------------------------
// GEMM bf16x3 (Q+K projections in ONE launch, z selects). 256 threads,
// 8 warps of 64x32 tiles, 128x128 block tile, 2-stage cp.async, 2 CTAs/SM.
// z=0 -> g_Q16 (+bq, *0.125), z=1 -> g_K16 (+bk). fp16 outputs.
// ---------------------------------------------------------------------------
#define BM 128
#define BN 128
#define BK 32
#define KLD 40
#define G2STGE (4*128*KLD)              // elems per stage (4 planes)
#define G2SMEM (2*G2STGE*2)             // 81920 bytes

__global__ __launch_bounds__(256, 2) void gemm2_kernel(
    const float* __restrict__ bq, const float* __restrict__ bk)
{
    extern __shared__ __align__(16) char sm[];
    uint32_t smb = (uint32_t)__cvta_generic_to_shared(sm);

    int sel = blockIdx.z;
    const float* bias = sel ? bk : bq;
    const __nv_bfloat16* Ah = g_Ih + (size_t)sel * Mtot * Dd;
    const __nv_bfloat16* Al = g_Il + (size_t)sel * Mtot * Dd;
    const __nv_bfloat16* Wh_ = g_Wh + ((size_t)sel << 20);
    const __nv_bfloat16* Wl_ = g_Wl + ((size_t)sel << 20);

    int t = threadIdx.x;
    int lane = t & 31, wid = t >> 5;
    int g = lane >> 2, qi = lane & 3;
    int wm = wid & 1;            // 0..1 -> 64-row strip
    int wn = wid >> 1;           // 0..3 -> 32-col strip
    int m0 = blockIdx.y * BM, n0 = blockIdx.x * BN;

    float c[4][4][4];
    #pragma unroll
    for (int mi = 0; mi < 4; mi++)
        #pragma unroll
        for (int ni = 0; ni < 4; ni++)
            #pragma unroll
            for (int x = 0; x < 4; x++) c[mi][ni][x] = 0.f;

    auto issue = [&](int k0, int st) {
        #pragma unroll
        for (int i = 0; i < 8; i++) {
            int id = t + i * 256;            // 0..2047
            int p = id >> 9;
            int r = (id >> 2) & 127;
            int c8 = (id & 3) << 3;
            uint32_t d = smb + (uint32_t)(st * G2STGE + p * 128 * KLD + r * KLD + c8) * 2;
            const __nv_bfloat16* src;
            if (p == 0)      src = Ah  + (size_t)(m0 + r) * Dd + k0 + c8;
            else if (p == 1) src = Al  + (size_t)(m0 + r) * Dd + k0 + c8;
            else if (p == 2) src = Wh_ + (size_t)(n0 + r) * Dd + k0 + c8;
            else             src = Wl_ + (size_t)(n0 + r) * Dd + k0 + c8;
            cp16(d, src);
        }
    };

    int arow = (lane & 7) + ((lane >> 3) & 1) * 8;
    int acol = ((lane >> 4) & 1) * 8;
    int bl_ = lane & 15;
    int brow = bl_ & 7;
    int bcol = ((bl_ >> 3) & 1) * 8;

    issue(0, 0);
    asm volatile("cp.async.commit_group;\n");

    const int NKT = Dd / BK;   // 32
    for (int kt = 0; kt < NKT; kt++) {
        if (kt + 1 < NKT) issue((kt + 1) * BK, (kt + 1) & 1);
        asm volatile("cp.async.commit_group;\n");
        asm volatile("cp.async.wait_group 1;\n");
        __syncthreads();

        uint32_t sb = smb + (uint32_t)((kt & 1) * G2STGE) * 2;
        uint32_t pAh = sb;
        uint32_t pAl = sb + 128 * KLD * 2;
        uint32_t pBh = sb + 2 * 128 * KLD * 2;
        uint32_t pBl = sb + 3 * 128 * KLD * 2;

        #pragma unroll
        for (int ks = 0; ks < 2; ks++) {
            uint32_t ah[4][4], al2[4][4], bh[4][2], bl2[4][2];
            #pragma unroll
            for (int mi = 0; mi < 4; mi++) {
                uint32_t off = (uint32_t)((wm * 64 + mi * 16 + arow) * KLD
                                          + ks * 16 + acol) * 2;
                ldsm_x4(ah[mi], pAh + off);
                ldsm_x4(al2[mi], pAl + off);
            }
            #pragma unroll
            for (int ni = 0; ni < 4; ni++) {
                uint32_t off = (uint32_t)((wn * 32 + ni * 8 + brow) * KLD
                                          + ks * 16 + bcol) * 2;
                ldsm_x2(bh[ni], pBh + off);
                ldsm_x2(bl2[ni], pBl + off);
            }
            #pragma unroll
            for (int mi = 0; mi < 4; mi++)
                #pragma unroll
                for (int ni = 0; ni < 4; ni++) {
                    mma_bf16(c[mi][ni], ah[mi], bh[ni][0], bh[ni][1]);
                    mma_bf16(c[mi][ni], ah[mi], bl2[ni][0], bl2[ni][1]);
                    mma_bf16(c[mi][ni], al2[mi], bh[ni][0], bh[ni][1]);
                }
        }
        __syncthreads();   // protect stage kt before it is re-issued (kt+2)
    }

    __half* D = sel ? g_K16 : g_Q16;
    float scale = sel ? 1.0f : 0.125f;

    #pragma unroll
    for (int mi = 0; mi < 4; mi++) {
        int R0 = m0 + wm * 64 + mi * 16 + g;
        int bb = R0 >> 11, srow = R0 & 2047;
        #pragma unroll
        for (int ni = 0; ni < 4; ni++) {
            int C0 = n0 + wn * 32 + ni * 8 + 2 * qi;
            int hh = C0 >> 6, d = C0 & 63;
            float2 b2 = *(const float2*)(bias + C0);
            size_t off0 = (((size_t)(bb * Hh + hh)) * Ss + srow) * HDd + d;
            *(__half2*)(D + off0) =
                __floats2half2_rn((c[mi][ni][0] + b2.x) * scale,
                                  (c[mi][ni][1] + b2.y) * scale);
            *(__half2*)(D + off0 + 512) =
                __floats2half2_rn((c[mi][ni][2] + b2.x) * scale,
                                  (c[mi][ni][3] + b2.y) * scale);
        }
    }
}

// ---------------------------------------------------------------------------
// GEMM fp16 single-pass (V projection, out projection). 256 threads,
// 8 warps of 64x32 tiles, 2-stage cp.async.
// dst 2 -> V head-split fp16 (+bias). dst 3 -> fp32 g_Y.
// ---------------------------------------------------------------------------
#define GFSTGE (2*128*KLD)              // elems per stage (2 planes)
#define GFSMEM (2*GFSTGE*2)             // 40960 bytes

__global__ __launch_bounds__(256, 2) void gemm_f16_kernel(
    int asel, const float* __restrict__ bias, int dst)
{
    extern __shared__ __align__(16) char sm[];
    uint32_t smb = (uint32_t)__cvta_generic_to_shared(sm);

    const __half* A = (asel == 2) ? g_Iv16 : g_C16;
    const __half* W = (asel == 2) ? g_Wv16 : g_Wo16;

    int t = threadIdx.x;
    int lane = t & 31, wid = t >> 5;
    int g = lane >> 2, qi = lane & 3;
    int wm = wid & 1;
    int wn = wid >> 1;
    int m0 = blockIdx.y * BM, n0 = blockIdx.x * BN;

    float c[4][4][4];
    #pragma unroll
    for (int mi = 0; mi < 4; mi++)
        #pragma unroll
        for (int ni = 0; ni < 4; ni++)
            #pragma unroll
            for (int x = 0; x < 4; x++) c[mi][ni][x] = 0.f;

    auto issue = [&](int k0, int st) {
        #pragma unroll
        for (int i = 0; i < 4; i++) {
            int id = t + i * 256;            // 0..1023
            int p = id >> 9;                 // 0=A, 1=W
            int q = id & 511;
            int r = q >> 2;
            int c8 = (q & 3) << 3;
            uint32_t d = smb + (uint32_t)(st * GFSTGE + p * 128 * KLD + r * KLD + c8) * 2;
            const __half* src = (p == 0) ? (A + (size_t)(m0 + r) * Dd + k0 + c8)
                                         : (W + (size_t)(n0 + r) * Dd + k0 + c8);
            cp16(d, src);
        }
    };

    int arow = (lane & 7) + ((lane >> 3) & 1) * 8;
    int acol = ((lane >> 4) & 1) * 8;
    int bl_ = lane & 15;
    int brow = bl_ & 7;
    int bcol = ((bl_ >> 3) & 1) * 8;

    issue(0, 0);
    asm volatile("cp.async.commit_group;\n");

    const int NKT = Dd / BK;
    for (int kt = 0; kt < NKT; kt++) {
        if (kt + 1 < NKT) issue((kt + 1) * BK, (kt + 1) & 1);
        asm volatile("cp.async.commit_group;\n");
        asm volatile("cp.async.wait_group 1;\n");
        __syncthreads();

        uint32_t sb = smb + (uint32_t)((kt & 1) * GFSTGE) * 2;
        uint32_t pA = sb;
        uint32_t pB = sb + 128 * KLD * 2;

        #pragma unroll
        for (int ks = 0; ks < 2; ks++) {
            uint32_t a[4][4], b[4][2];
            #pragma unroll
            for (int mi = 0; mi < 4; mi++) {
                uint32_t off = (uint32_t)((wm * 64 + mi * 16 + arow) * KLD
                                          + ks * 16 + acol) * 2;
                ldsm_x4(a[mi], pA + off);
            }
            #pragma unroll
            for (int ni = 0; ni < 4; ni++) {
                uint32_t off = (uint32_t)((wn * 32 + ni * 8 + brow) * KLD
                                          + ks * 16 + bcol) * 2;
                ldsm_x2(b[ni], pB + off);
            }
            #pragma unroll
            for (int mi = 0; mi < 4; mi++)
                #pragma unroll
                for (int ni = 0; ni < 4; ni++)
                    mma_f16(c[mi][ni], a[mi], b[ni][0], b[ni][1]);
        }
        __syncthreads();
    }

    if (dst == 3) {
        #pragma unroll
        for (int mi = 0; mi < 4; mi++) {
            int R0 = m0 + wm * 64 + mi * 16 + g;
            #pragma unroll
            for (int ni = 0; ni < 4; ni++) {
                int C0 = n0 + wn * 32 + ni * 8 + 2 * qi;
                *(float2*)(g_Y + (size_t)R0 * Dd + C0) =
                    make_float2(c[mi][ni][0], c[mi][ni][1]);
                *(float2*)(g_Y + (size_t)(R0 + 8) * Dd + C0) =
                    make_float2(c[mi][ni][2], c[mi][ni][3]);
            }
        }
        return;
    }

    // dst == 2: V head-split fp16 (+bias)
    #pragma unroll
    for (int mi = 0; mi < 4; mi++) {
        int R0 = m0 + wm * 64 + mi * 16 + g;
        int bb = R0 >> 11, srow = R0 & 2047;
        #pragma unroll
        for (int ni = 0; ni < 4; ni++) {
            int C0 = n0 + wn * 32 + ni * 8 + 2 * qi;
            int hh = C0 >> 6, d = C0 & 63;
            float2 b2 = *(const float2*)(bias + C0);
            size_t off0 = (((size_t)(bb * Hh + hh)) * Ss + srow) * HDd + d;
            *(__half2*)(g_V16 + off0) =
                __floats2half2_rn(c[mi][ni][0] + b2.x, c[mi][ni][1] + b2.y);
            *(__half2*)(g_V16 + off0 + 512) =
                __floats2half2_rn(c[mi][ni][2] + b2.x, c[mi][ni][3] + b2.y);
        }
    }
}

// ---------------------------------------------------------------------------
// Transpose V per (b,h): [s][d] -> [d][s] (fp16 single plane).
// ---------------------------------------------------------------------------
__global__ __launch_bounds__(256) void vtrans_kernel()
{
    __shared__ __half sT[64 * 72];
    int t = threadIdx.x;
    int bh = blockIdx.y;
    int s0 = blockIdx.x * 64;
    const __half* V = g_V16 + (size_t)bh * (Ss * HDd);

    #pragma unroll
    for (int i = 0; i < 2; i++) {
        int idx = t + i * 256;
        int row = idx >> 3, c8 = (idx & 7) << 3;
        *(float4*)&sT[row * 72 + c8] = *(const float4*)&V[(size_t)(s0 + row) * HDd + c8];
    }
    __syncthreads();

    #pragma unroll
    for (int i = 0; i < 2; i++) {
        int idx = t + i * 256;
        int d = idx & 63, s8 = (idx >> 6) << 3;
        uint32_t outv[4];
        #pragma unroll
        for (int k = 0; k < 4; k++) {
            __half2 hh;
            hh.x = sT[(s8 + 2 * k) * 72 + d];
            hh.y = sT[(s8 + 2 * k + 1) * 72 + d];
            outv[k] = *(uint32_t*)&hh;
        }
        *(float4*)&g_Vt16[((size_t)bh * HDd + d) * Ss + s0 + s8] = *(float4*)outv;
    }
}

// ---------------------------------------------------------------------------
// Attention: QK^T fp16x1, exp in regs, P->fp16, PV fp16x1, fused norm tail.
// smem: 2 stages x 2 planes (K fp16 + Vt fp16) x 64x72 = 36864 B. 2 CTAs/SM.
// ---------------------------------------------------------------------------
#define APL   (64*72*2)
#define ASTGB (2*APL)
#define ATTN_SMEM (2*ASTGB)     // 36864

__global__ __launch_bounds__(256, 2) void attn_mma_kernel(float* __restrict__ attn_ext,
                                                          int use_scratch)
{
    float* attn = use_scratch ? g_attn_scratch : attn_ext;

    extern __shared__ __align__(16) char dynsm[];
    uint32_t smb = (uint32_t)__cvta_generic_to_shared(dynsm);

    int t = threadIdx.x;
    int lane = t & 31, w = t >> 5;
    int g = lane >> 2, qi = lane & 3;
    int bh = blockIdx.y, q0 = blockIdx.x * 128;
    int b = bh >> 4, h = bh & 15;

    const __half* Qp = g_Q16  + (size_t)bh * (Ss * HDd);
    const __half* Kp = g_K16  + (size_t)bh * (Ss * HDd);
    const __half* Vt = g_Vt16 + (size_t)bh * (Ss * HDd);

    int qrow = q0 + w * 16 + g;

    // Q A-fragments in registers (fp16; Q pre-scaled by 0.125)
    uint32_t qf[4][4];
    #pragma unroll
    for (int kk = 0; kk < 4; kk++) {
        int c0 = kk * 16 + 2 * qi;
        qf[kk][0] = *(const uint32_t*)&Qp[(size_t)qrow * HDd + c0];
        qf[kk][1] = *(const uint32_t*)&Qp[(size_t)(qrow + 8) * HDd + c0];
        qf[kk][2] = *(const uint32_t*)&Qp[(size_t)qrow * HDd + c0 + 8];
        qf[kk][3] = *(const uint32_t*)&Qp[(size_t)(qrow + 8) * HDd + c0 + 8];
    }

    float o[8][4];
    #pragma unroll
    for (int j = 0; j < 8; j++)
        #pragma unroll
        for (int x = 0; x < 4; x++) o[j][x] = 0.f;
    float rs0 = 0.f, rs1 = 0.f;

    auto issue_stage = [&](int kt, int st) {
        #pragma unroll
        for (int i = 0; i < 2; i++) {
            int idx = t + i * 256;
            int row = idx >> 3, c8 = (idx & 7) << 3;
            uint32_t doff = smb + st * ASTGB + (row * 72 + c8) * 2;
            cp16(doff,       &Kp[(size_t)(kt * 64 + row) * HDd + c8]);
            cp16(doff + APL, &Vt[(size_t)row * Ss + kt * 64 + c8]);
        }
    };

    issue_stage(0, 0);
    asm volatile("cp.async.commit_group;\n");

    for (int kt = 0; kt < Ss / 64; kt++) {
        if (kt + 1 < Ss / 64) issue_stage(kt + 1, (kt + 1) & 1);
        asm volatile("cp.async.commit_group;\n");
        asm volatile("cp.async.wait_group 1;\n");
        __syncthreads();

        const __half* sK = (const __half*)(dynsm + (kt & 1) * ASTGB);
        const __half* sV = sK + 64 * 72;

        uint32_t pfh[4][4];

        #pragma unroll
        for (int j = 0; j < 8; j++) {
            float s[4] = {0.f, 0.f, 0.f, 0.f};
            #pragma unroll
            for (int kk = 0; kk < 4; kk++) {
                const __half* kb = &sK[(j * 8 + g) * 72 + kk * 16 + 2 * qi];
                uint32_t b0 = *(const uint32_t*)kb;
                uint32_t b1 = *(const uint32_t*)(kb + 8);
                mma_f16(s, qf[kk], b0, b1);
            }
            float p0 = __expf(s[0]), p1 = __expf(s[1]);
            float p2 = __expf(s[2]), p3 = __expf(s[3]);
            rs0 += p0 + p1;
            rs1 += p2 + p3;

            size_t coff = (size_t)kt * 64 + j * 8 + 2 * qi;
            *(float2*)&attn[((size_t)bh * Ss + qrow) * Ss + coff]     = make_float2(p0, p1);
            *(float2*)&attn[((size_t)bh * Ss + qrow + 8) * Ss + coff] = make_float2(p2, p3);

            int kk2 = j >> 1, rb = (j & 1) << 1;
            __half2 h01 = __floats2half2_rn(p0, p1);
            __half2 h23 = __floats2half2_rn(p2, p3);
            pfh[kk2][rb]     = *(uint32_t*)&h01;
            pfh[kk2][rb + 1] = *(uint32_t*)&h23;
        }

        #pragma unroll
        for (int j = 0; j < 8; j++) {
            #pragma unroll
            for (int kk = 0; kk < 4; kk++) {
                const __half* vb = &sV[(j * 8 + g) * 72 + kk * 16 + 2 * qi];
                uint32_t b0 = *(const uint32_t*)vb;
                uint32_t b1 = *(const uint32_t*)(vb + 8);
                mma_f16(o[j], pfh[kk], b0, b1);
            }
        }
        __syncthreads();
    }

    rs0 += __shfl_xor_sync(0xffffffffu, rs0, 1);
    rs0 += __shfl_xor_sync(0xffffffffu, rs0, 2);
    rs1 += __shfl_xor_sync(0xffffffffu, rs1, 1);
    rs1 += __shfl_xor_sync(0xffffffffu, rs1, 2);
    float il0 = 1.f / rs0, il1 = 1.f / rs1;

    // ctx out (normalized) as fp16
    #pragma unroll
    for (int j = 0; j < 8; j++) {
        float v0 = o[j][0] * il0, v1 = o[j][1] * il0;
        float v2 = o[j][2] * il1, v3 = o[j][3] * il1;
        size_t off0 = ((size_t)(b * Ss) + qrow) * Dd + h * HDd + j * 8 + 2 * qi;
        size_t off1 = off0 + (size_t)8 * Dd;
        *(__half2*)&g_C16[off0] = __floats2half2_rn(v0, v1);
        *(__half2*)&g_C16[off1] = __floats2half2_rn(v2, v3);
    }

    // Fused normalize tail (in-place fp32 rescan; lines still warm)
    if (!use_scratch) {
        float* sInvl = (float*)dynsm;
        __syncthreads();
        if (qi == 0) {
            sInvl[w * 16 + g]     = il0;
            sInvl[w * 16 + g + 8] = il1;
        }
        __syncthreads();
        float* base = attn + ((size_t)bh * Ss + q0) * Ss;
        for (int r = 0; r < 128; r++) {
            float il = sInvl[r];
            float* p = base + (size_t)r * Ss;
            #pragma unroll
            for (int i = 0; i < 2; i++) {
                int c4 = (t + i * 256) << 2;
                float4 v = *(float4*)(p + c4);
                v.x *= il; v.y *= il; v.z *= il; v.w *= il;
                *(float4*)(p + c4) = v;
            }
        }
    }
}

// ---------------------------------------------------------------------------
// LayerNorm over D=1024 per row; fuses out-proj bias + residual(query).
// ---------------------------------------------------------------------------
__global__ __launch_bounds__(256) void ln_kernel(const float* __restrict__ gamma,
                                                 const float* __restrict__ beta,
                                                 const float* __restrict__ bo,
                                                 const float* __restrict__ query,
                                                 float* __restrict__ outext,
                                                 int use_internal)
{
    float* out = use_internal ? g_Y : outext;
    int row = blockIdx.x;
    const float* y = g_Y + (size_t)row * Dd;
    const float* q = query + (size_t)row * Dd;
    int t = threadIdx.x;
    int lane = t & 31, warp = t >> 5;
    __shared__ float red[8];

    int c = t << 2;
    float4 x  = *(const float4*)(y + c);
    float4 qv = *(const float4*)(q + c);
    float4 bv = *(const float4*)(bo + c);
    x.x += qv.x + bv.x; x.y += qv.y + bv.y;
    x.z += qv.z + bv.z; x.w += qv.w + bv.w;

    float sum = x.x + x.y + x.z + x.w;
    #pragma unroll
    for (int o = 16; o > 0; o >>= 1) sum += __shfl_xor_sync(0xffffffffu, sum, o);
    if (lane == 0) red[warp] = sum;
    __syncthreads();
    float tot = 0.f;
    #pragma unroll
    for (int w = 0; w < 8; w++) tot += red[w];
    float mean = tot * (1.f / Dd);

    float dx[4] = {x.x - mean, x.y - mean, x.z - mean, x.w - mean};
    float vs = dx[0]*dx[0] + dx[1]*dx[1] + dx[2]*dx[2] + dx[3]*dx[3];
    #pragma unroll
    for (int o = 16; o > 0; o >>= 1) vs += __shfl_xor_sync(0xffffffffu, vs, o);
    __syncthreads();
    if (lane == 0) red[warp] = vs;
    __syncthreads();
    float vtot = 0.f;
    #pragma unroll
    for (int w = 0; w < 8; w++) vtot += red[w];
    float r = rsqrtf(vtot * (1.f / Dd) + 1e-5f);

    float4 o4;
    o4.x = dx[0] * r * gamma[c + 0] + beta[c + 0];
    o4.y = dx[1] * r * gamma[c + 1] + beta[c + 1];
    o4.z = dx[2] * r * gamma[c + 2] + beta[c + 2];
    o4.w = dx[3] * r * gamma[c + 3] + beta[c + 3];
    *(float4*)(out + (size_t)row * Dd + c) = o4;
}

// ---------------------------------------------------------------------------
extern "C" void kernel_launch(void* const* d_in, const int* in_sizes, int n_in,
                              void* d_out, int out_size)
{
    const float* query = (const float*)d_in[0];
    const float* key_t = (const float*)d_in[1];
    const float* value = (const float*)d_in[2];
    const float* Wq    = (const float*)d_in[3];
    const float* bq    = (const float*)d_in[4];
    const float* Wk    = (const float*)d_in[5];
    const float* bk    = (const float*)d_in[6];
    const float* Wv    = (const float*)d_in[7];
    const float* bv    = (const float*)d_in[8];
    const float* Wo    = (const float*)d_in[9];
    const float* bo    = (const float*)d_in[10];
    const float* gamma = (const float*)d_in[11];
    const float* beta  = (const float*)d_in[12];

    float* out = (float*)d_out;
    const long long BSD = (long long)Bb * Ss * Dd;
    const long long ATT = (long long)Bb * Hh * Ss * (long long)Ss;

    float* attn_ext = out;
    int use_scratch = 1;
    float* out_ext = out;
    int out_internal = 0;
    if ((long long)out_size >= BSD + ATT) {
        attn_ext = out + BSD;
        use_scratch = 0;
    } else if ((long long)out_size == ATT) {
        attn_ext = out;
        use_scratch = 0;
        out_internal = 1;
    }

    cudaFuncSetAttribute(attn_mma_kernel,
                         cudaFuncAttributeMaxDynamicSharedMemorySize, ATTN_SMEM);
    cudaFuncSetAttribute(gemm2_kernel,
                         cudaFuncAttributeMaxDynamicSharedMemorySize, G2SMEM);
    cudaFuncSetAttribute(gemm_f16_kernel,
                         cudaFuncAttributeMaxDynamicSharedMemorySize, GFSMEM);

    prep_w_kernel<<<dim3(1024, 4), 256>>>(Wq, Wk, Wv, Wo);
    prep_i_kernel<<<dim3(8192, 3), 256>>>(query, key_t, value);

    dim3 ggrid(Dd / BN, Mtot / BM);         // (8, 64)
    dim3 ggrid2(Dd / BN, Mtot / BM, 2);     // Q+K fused
    gemm2_kernel<<<ggrid2, 256, G2SMEM>>>(bq, bk);
    gemm_f16_kernel<<<ggrid, 256, GFSMEM>>>(2, bv, 2);

    vtrans_kernel<<<dim3(Ss / 64, Bb * Hh), 256>>>();

    attn_mma_kernel<<<dim3(Ss / 128, Bb * Hh), 256, ATTN_SMEM>>>(attn_ext, use_scratch);

    gemm_f16_kernel<<<ggrid, 256, GFSMEM>>>(3, nullptr, 3);

    ln_kernel<<<Mtot, 256>>>(gamma, beta, bo, query, out_ext, out_internal);
}

// round 16
// speedup vs baseline: 1.3171x; 1.2121x over previous
#include <cuda_runtime.h>
#include <cuda_bf16.h>
#include <cuda_fp16.h>
#include <math.h>
#include <cstdint>
#include <cstring>

#define Bb   4
#define Ss   2048
#define Dd   1024
#define Hh   16
#define HDd  64
#define Mtot (Bb*Ss)            // 8192
#define NBH  (Bb*Hh*Ss*HDd)     // 8388608

// Scratch (__device__ globals; allocation-free rule)
__device__ __half g_Q16[NBH], g_K16[NBH];           // Q,K fp16 head-split
__device__ __half g_V16[NBH], g_Vt16[NBH];          // V fp16 (+transposed)
__device__ __half g_C16[Bb*Ss*Dd];                  // ctx fp16
__device__ __half g_W16[4u*1024*1024];              // Wq,Wk,Wv,Wo fp16
__device__ __half g_I16[3u*Mtot*Dd];                // query,key_t,value fp16
__device__ float  g_Y[Bb*Ss*Dd];                    // out-proj raw
__device__ float  g_attn_scratch[(size_t)Bb*Hh*Ss*Ss];

// ---------------------------------------------------------------------------
// fp16 mma: D += A(16x16) * B(16x8), fp32 accum.
__device__ __forceinline__ void mma_f16(float* c, const uint32_t* a,
                                        uint32_t b0, uint32_t b1) {
    asm volatile(
        "mma.sync.aligned.m16n8k16.row.col.f32.f16.f16.f32 "
        "{%0,%1,%2,%3}, {%4,%5,%6,%7}, {%8,%9}, {%0,%1,%2,%3};\n"
        : "+f"(c[0]), "+f"(c[1]), "+f"(c[2]), "+f"(c[3])
        : "r"(a[0]), "r"(a[1]), "r"(a[2]), "r"(a[3]), "r"(b0), "r"(b1));
}

__device__ __forceinline__ void ldsm_x4(uint32_t* r, uint32_t addr) {
    asm volatile("ldmatrix.sync.aligned.m8n8.x4.shared.b16 {%0,%1,%2,%3}, [%4];\n"
                 : "=r"(r[0]), "=r"(r[1]), "=r"(r[2]), "=r"(r[3]) : "r"(addr));
}
__device__ __forceinline__ void ldsm_x2(uint32_t* r, uint32_t addr) {
    asm volatile("ldmatrix.sync.aligned.m8n8.x2.shared.b16 {%0,%1}, [%2];\n"
                 : "=r"(r[0]), "=r"(r[1]) : "r"(addr));
}
__device__ __forceinline__ void cp16(uint32_t daddr, const void* src) {
    asm volatile("cp.async.cg.shared.global [%0], [%1], 16;\n" :: "r"(daddr), "l"(src));
}

// ---------------------------------------------------------------------------
// Pre-convert weights / inputs to fp16.
// ---------------------------------------------------------------------------
__global__ __launch_bounds__(256) void prep_w_kernel(
    const float* __restrict__ Wq, const float* __restrict__ Wk,
    const float* __restrict__ Wv, const float* __restrict__ Wo)
{
    int w = blockIdx.y;
    const float* W = (w == 0) ? Wq : (w == 1) ? Wk : (w == 2) ? Wv : Wo;
    __half* d = g_W16 + ((size_t)w << 20);
    size_t i = (size_t)blockIdx.x * 256 + threadIdx.x;   // float4 index
    float4 v = *(const float4*)(W + i * 4);
    *(__half2*)(d + i * 4)     = __floats2half2_rn(v.x, v.y);
    *(__half2*)(d + i * 4 + 2) = __floats2half2_rn(v.z, v.w);
}

__global__ __launch_bounds__(256) void prep_i_kernel(
    const float* __restrict__ q, const float* __restrict__ k,
    const float* __restrict__ v)
{
    int w = blockIdx.y;
    const float* X = (w == 0) ? q : (w == 1) ? k : v;
    __half* d = g_I16 + (size_t)w * Mtot * Dd;
    size_t i = (size_t)blockIdx.x * 256 + threadIdx.x;
    float4 val = *(const float4*)(X + i * 4);
    *(__half2*)(d + i * 4)     = __floats2half2_rn(val.x, val.y);
    *(__half2*)(d + i * 4 + 2) = __floats2half2_rn(val.z, val.w);
}

// ---------------------------------------------------------------------------
// GEMM fp16 single-pass. 256 threads, 8 warps of 64x32 tiles, 128x128 block,
// 2-stage cp.async, 2 CTAs/SM.
// oproj=0: QKV fused, z selects {Q(+bq,*0.125), K(+bk), V(+bv)} head-split fp16.
// oproj=1: ctx @ Wo^T -> fp32 g_Y.
// ---------------------------------------------------------------------------
#define BM 128
#define BN 128
#define BK 32
#define KLD 40
#define GFSTGE (2*128*KLD)              // elems per stage (2 planes)
#define GFSMEM (2*GFSTGE*2)             // 40960 bytes

__global__ __launch_bounds__(256, 2) void gemm_f16_kernel(
    const float* __restrict__ bq, const float* __restrict__ bk,
    const float* __restrict__ bv, int oproj)
{
    extern __shared__ __align__(16) char sm[];
    uint32_t smb = (uint32_t)__cvta_generic_to_shared(sm);

    int sel = oproj ? 3 : blockIdx.z;
    const __half* A = oproj ? g_C16 : (g_I16 + (size_t)sel * Mtot * Dd);
    const __half* W = g_W16 + ((size_t)sel << 20);
    const float* bias = (sel == 0) ? bq : (sel == 1) ? bk : bv;

    int t = threadIdx.x;
    int lane = t & 31, wid = t >> 5;
    int g = lane >> 2, qi = lane & 3;
    int wm = wid & 1;
    int wn = wid >> 1;
    int m0 = blockIdx.y * BM, n0 = blockIdx.x * BN;

    float c[4][4][4];
    #pragma unroll
    for (int mi = 0; mi < 4; mi++)
        #pragma unroll
        for (int ni = 0; ni < 4; ni++)
            #pragma unroll
            for (int x = 0; x < 4; x++) c[mi][ni][x] = 0.f;

    auto issue = [&](int k0, int st) {
        #pragma unroll
        for (int i = 0; i < 4; i++) {
            int id = t + i * 256;            // 0..1023
            int p = id >> 9;                 // 0=A, 1=W
            int q = id & 511;
            int r = q >> 2;
            int c8 = (q & 3) << 3;
            uint32_t d = smb + (uint32_t)(st * GFSTGE + p * 128 * KLD + r * KLD + c8) * 2;
            const __half* src = (p == 0) ? (A + (size_t)(m0 + r) * Dd + k0 + c8)
                                         : (W + (size_t)(n0 + r) * Dd + k0 + c8);
            cp16(d, src);
        }
    };

    int arow = (lane & 7) + ((lane >> 3) & 1) * 8;
    int acol = ((lane >> 4) & 1) * 8;
    int bl_ = lane & 15;
    int brow = bl_ & 7;
    int bcol = ((bl_ >> 3) & 1) * 8;

    issue(0, 0);
    asm volatile("cp.async.commit_group;\n");

    const int NKT = Dd / BK;
    for (int kt = 0; kt < NKT; kt++) {
        if (kt + 1 < NKT) issue((kt + 1) * BK, (kt + 1) & 1);
        asm volatile("cp.async.commit_group;\n");
        asm volatile("cp.async.wait_group 1;\n");
        __syncthreads();

        uint32_t sb = smb + (uint32_t)((kt & 1) * GFSTGE) * 2;
        uint32_t pA = sb;
        uint32_t pB = sb + 128 * KLD * 2;

        #pragma unroll
        for (int ks = 0; ks < 2; ks++) {
            uint32_t a[4][4], b[4][2];
            #pragma unroll
            for (int mi = 0; mi < 4; mi++) {
                uint32_t off = (uint32_t)((wm * 64 + mi * 16 + arow) * KLD
                                          + ks * 16 + acol) * 2;
                ldsm_x4(a[mi], pA + off);
            }
            #pragma unroll
            for (int ni = 0; ni < 4; ni++) {
                uint32_t off = (uint32_t)((wn * 32 + ni * 8 + brow) * KLD
                                          + ks * 16 + bcol) * 2;
                ldsm_x2(b[ni], pB + off);
            }
            #pragma unroll
            for (int mi = 0; mi < 4; mi++)
                #pragma unroll
                for (int ni = 0; ni < 4; ni++)
                    mma_f16(c[mi][ni], a[mi], b[ni][0], b[ni][1]);
        }
        __syncthreads();
    }

    if (oproj) {
        #pragma unroll
        for (int mi = 0; mi < 4; mi++) {
            int R0 = m0 + wm * 64 + mi * 16 + g;
            #pragma unroll
            for (int ni = 0; ni < 4; ni++) {
                int C0 = n0 + wn * 32 + ni * 8 + 2 * qi;
                *(float2*)(g_Y + (size_t)R0 * Dd + C0) =
                    make_float2(c[mi][ni][0], c[mi][ni][1]);
                *(float2*)(g_Y + (size_t)(R0 + 8) * Dd + C0) =
                    make_float2(c[mi][ni][2], c[mi][ni][3]);
            }
        }
        return;
    }

    // QKV: head-split fp16 (+bias; Q scaled by 0.125)
    __half* D = (sel == 0) ? g_Q16 : (sel == 1) ? g_K16 : g_V16;
    float scale = (sel == 0) ? 0.125f : 1.0f;

    #pragma unroll
    for (int mi = 0; mi < 4; mi++) {
        int R0 = m0 + wm * 64 + mi * 16 + g;
        int bb = R0 >> 11, srow = R0 & 2047;
        #pragma unroll
        for (int ni = 0; ni < 4; ni++) {
            int C0 = n0 + wn * 32 + ni * 8 + 2 * qi;
            int hh = C0 >> 6, d = C0 & 63;
            float2 b2 = *(const float2*)(bias + C0);
            size_t off0 = (((size_t)(bb * Hh + hh)) * Ss + srow) * HDd + d;
            *(__half2*)(D + off0) =
                __floats2half2_rn((c[mi][ni][0] + b2.x) * scale,
                                  (c[mi][ni][1] + b2.y) * scale);
            *(__half2*)(D + off0 + 512) =
                __floats2half2_rn((c[mi][ni][2] + b2.x) * scale,
                                  (c[mi][ni][3] + b2.y) * scale);
        }
    }
}

// ---------------------------------------------------------------------------
// Transpose V per (b,h): [s][d] -> [d][s] (fp16 single plane).
// ---------------------------------------------------------------------------
__global__ __launch_bounds__(256) void vtrans_kernel()
{
    __shared__ __half sT[64 * 72];
    int t = threadIdx.x;
    int bh = blockIdx.y;
    int s0 = blockIdx.x * 64;
    const __half* V = g_V16 + (size_t)bh * (Ss * HDd);

    #pragma unroll
    for (int i = 0; i < 2; i++) {
        int idx = t + i * 256;
        int row = idx >> 3, c8 = (idx & 7) << 3;
        *(float4*)&sT[row * 72 + c8] = *(const float4*)&V[(size_t)(s0 + row) * HDd + c8];
    }
    __syncthreads();

    #pragma unroll
    for (int i = 0; i < 2; i++) {
        int idx = t + i * 256;
        int d = idx & 63, s8 = (idx >> 6) << 3;
        uint32_t outv[4];
        #pragma unroll
        for (int k = 0; k < 4; k++) {
            __half2 hh;
            hh.x = sT[(s8 + 2 * k) * 72 + d];
            hh.y = sT[(s8 + 2 * k + 1) * 72 + d];
            outv[k] = *(uint32_t*)&hh;
        }
        *(float4*)&g_Vt16[((size_t)bh * HDd + d) * Ss + s0 + s8] = *(float4*)outv;
    }
}

// ---------------------------------------------------------------------------
// Attention: QK^T fp16x1, exp in regs, P->fp16, PV fp16x1, fused norm tail.
// smem: 2 stages x 2 planes (K fp16 + Vt fp16) x 64x72 = 36864 B. 2 CTAs/SM.
// ---------------------------------------------------------------------------
#define APL   (64*72*2)
#define ASTGB (2*APL)
#define ATTN_SMEM (2*ASTGB)     // 36864

__global__ __launch_bounds__(256, 2) void attn_mma_kernel(float* __restrict__ attn_ext,
                                                          int use_scratch)
{
    float* attn = use_scratch ? g_attn_scratch : attn_ext;

    extern __shared__ __align__(16) char dynsm[];
    uint32_t smb = (uint32_t)__cvta_generic_to_shared(dynsm);

    int t = threadIdx.x;
    int lane = t & 31, w = t >> 5;
    int g = lane >> 2, qi = lane & 3;
    int bh = blockIdx.y, q0 = blockIdx.x * 128;
    int b = bh >> 4, h = bh & 15;

    const __half* Qp = g_Q16  + (size_t)bh * (Ss * HDd);
    const __half* Kp = g_K16  + (size_t)bh * (Ss * HDd);
    const __half* Vt = g_Vt16 + (size_t)bh * (Ss * HDd);

    int qrow = q0 + w * 16 + g;

    // Q A-fragments in registers (fp16; Q pre-scaled by 0.125)
    uint32_t qf[4][4];
    #pragma unroll
    for (int kk = 0; kk < 4; kk++) {
        int c0 = kk * 16 + 2 * qi;
        qf[kk][0] = *(const uint32_t*)&Qp[(size_t)qrow * HDd + c0];
        qf[kk][1] = *(const uint32_t*)&Qp[(size_t)(qrow + 8) * HDd + c0];
        qf[kk][2] = *(const uint32_t*)&Qp[(size_t)qrow * HDd + c0 + 8];
        qf[kk][3] = *(const uint32_t*)&Qp[(size_t)(qrow + 8) * HDd + c0 + 8];
    }

    float o[8][4];
    #pragma unroll
    for (int j = 0; j < 8; j++)
        #pragma unroll
        for (int x = 0; x < 4; x++) o[j][x] = 0.f;
    float rs0 = 0.f, rs1 = 0.f;

    auto issue_stage = [&](int kt, int st) {
        #pragma unroll
        for (int i = 0; i < 2; i++) {
            int idx = t + i * 256;
            int row = idx >> 3, c8 = (idx & 7) << 3;
            uint32_t doff = smb + st * ASTGB + (row * 72 + c8) * 2;
            cp16(doff,       &Kp[(size_t)(kt * 64 + row) * HDd + c8]);
            cp16(doff + APL, &Vt[(size_t)row * Ss + kt * 64 + c8]);
        }
    };

    issue_stage(0, 0);
    asm volatile("cp.async.commit_group;\n");

    for (int kt = 0; kt < Ss / 64; kt++) {
        if (kt + 1 < Ss / 64) issue_stage(kt + 1, (kt + 1) & 1);
        asm volatile("cp.async.commit_group;\n");
        asm volatile("cp.async.wait_group 1;\n");
        __syncthreads();

        const __half* sK = (const __half*)(dynsm + (kt & 1) * ASTGB);
        const __half* sV = sK + 64 * 72;

        uint32_t pfh[4][4];

        #pragma unroll
        for (int j = 0; j < 8; j++) {
            float s[4] = {0.f, 0.f, 0.f, 0.f};
            #pragma unroll
            for (int kk = 0; kk < 4; kk++) {
                const __half* kb = &sK[(j * 8 + g) * 72 + kk * 16 + 2 * qi];
                uint32_t b0 = *(const uint32_t*)kb;
                uint32_t b1 = *(const uint32_t*)(kb + 8);
                mma_f16(s, qf[kk], b0, b1);
            }
            float p0 = __expf(s[0]), p1 = __expf(s[1]);
            float p2 = __expf(s[2]), p3 = __expf(s[3]);
            rs0 += p0 + p1;
            rs1 += p2 + p3;

            size_t coff = (size_t)kt * 64 + j * 8 + 2 * qi;
            *(float2*)&attn[((size_t)bh * Ss + qrow) * Ss + coff]     = make_float2(p0, p1);
            *(float2*)&attn[((size_t)bh * Ss + qrow + 8) * Ss + coff] = make_float2(p2, p3);

            int kk2 = j >> 1, rb = (j & 1) << 1;
            __half2 h01 = __floats2half2_rn(p0, p1);
            __half2 h23 = __floats2half2_rn(p2, p3);
            pfh[kk2][rb]     = *(uint32_t*)&h01;
            pfh[kk2][rb + 1] = *(uint32_t*)&h23;
        }

        #pragma unroll
        for (int j = 0; j < 8; j++) {
            #pragma unroll
            for (int kk = 0; kk < 4; kk++) {
                const __half* vb = &sV[(j * 8 + g) * 72 + kk * 16 + 2 * qi];
                uint32_t b0 = *(const uint32_t*)vb;
                uint32_t b1 = *(const uint32_t*)(vb + 8);
                mma_f16(o[j], pfh[kk], b0, b1);
            }
        }
        __syncthreads();
    }

    rs0 += __shfl_xor_sync(0xffffffffu, rs0, 1);
    rs0 += __shfl_xor_sync(0xffffffffu, rs0, 2);
    rs1 += __shfl_xor_sync(0xffffffffu, rs1, 1);
    rs1 += __shfl_xor_sync(0xffffffffu, rs1, 2);
    float il0 = 1.f / rs0, il1 = 1.f / rs1;

    // ctx out (normalized) as fp16
    #pragma unroll
    for (int j = 0; j < 8; j++) {
        float v0 = o[j][0] * il0, v1 = o[j][1] * il0;
        float v2 = o[j][2] * il1, v3 = o[j][3] * il1;
        size_t off0 = ((size_t)(b * Ss) + qrow) * Dd + h * HDd + j * 8 + 2 * qi;
        size_t off1 = off0 + (size_t)8 * Dd;
        *(__half2*)&g_C16[off0] = __floats2half2_rn(v0, v1);
        *(__half2*)&g_C16[off1] = __floats2half2_rn(v2, v3);
    }

    // Fused normalize tail (in-place fp32 rescan; lines still warm)
    if (!use_scratch) {
        float* sInvl = (float*)dynsm;
        __syncthreads();
        if (qi == 0) {
            sInvl[w * 16 + g]     = il0;
            sInvl[w * 16 + g + 8] = il1;
        }
        __syncthreads();
        float* base = attn + ((size_t)bh * Ss + q0) * Ss;
        for (int r = 0; r < 128; r++) {
            float il = sInvl[r];
            float* p = base + (size_t)r * Ss;
            #pragma unroll
            for (int i = 0; i < 2; i++) {
                int c4 = (t + i * 256) << 2;
                float4 v = *(float4*)(p + c4);
                v.x *= il; v.y *= il; v.z *= il; v.w *= il;
                *(float4*)(p + c4) = v;
            }
        }
    }
}

// ---------------------------------------------------------------------------
// LayerNorm over D=1024 per row; fuses out-proj bias + residual(query).
// ---------------------------------------------------------------------------
__global__ __launch_bounds__(256) void ln_kernel(const float* __restrict__ gamma,
                                                 const float* __restrict__ beta,
                                                 const float* __restrict__ bo,
                                                 const float* __restrict__ query,
                                                 float* __restrict__ outext,
                                                 int use_internal)
{
    float* out = use_internal ? g_Y : outext;
    int row = blockIdx.x;
    const float* y = g_Y + (size_t)row * Dd;
    const float* q = query + (size_t)row * Dd;
    int t = threadIdx.x;
    int lane = t & 31, warp = t >> 5;
    __shared__ float red[8];

    int c = t << 2;
    float4 x  = *(const float4*)(y + c);
    float4 qv = *(const float4*)(q + c);
    float4 bv = *(const float4*)(bo + c);
    x.x += qv.x + bv.x; x.y += qv.y + bv.y;
    x.z += qv.z + bv.z; x.w += qv.w + bv.w;

    float sum = x.x + x.y + x.z + x.w;
    #pragma unroll
    for (int o = 16; o > 0; o >>= 1) sum += __shfl_xor_sync(0xffffffffu, sum, o);
    if (lane == 0) red[warp] = sum;
    __syncthreads();
    float tot = 0.f;
    #pragma unroll
    for (int w = 0; w < 8; w++) tot += red[w];
    float mean = tot * (1.f / Dd);

    float dx[4] = {x.x - mean, x.y - mean, x.z - mean, x.w - mean};
    float vs = dx[0]*dx[0] + dx[1]*dx[1] + dx[2]*dx[2] + dx[3]*dx[3];
    #pragma unroll
    for (int o = 16; o > 0; o >>= 1) vs += __shfl_xor_sync(0xffffffffu, vs, o);
    __syncthreads();
    if (lane == 0) red[warp] = vs;
    __syncthreads();
    float vtot = 0.f;
    #pragma unroll
    for (int w = 0; w < 8; w++) vtot += red[w];
    float r = rsqrtf(vtot * (1.f / Dd) + 1e-5f);

    float4 o4;
    o4.x = dx[0] * r * gamma[c + 0] + beta[c + 0];
    o4.y = dx[1] * r * gamma[c + 1] + beta[c + 1];
    o4.z = dx[2] * r * gamma[c + 2] + beta[c + 2];
    o4.w = dx[3] * r * gamma[c + 3] + beta[c + 3];
    *(float4*)(out + (size_t)row * Dd + c) = o4;
}

// ---------------------------------------------------------------------------
extern "C" void kernel_launch(void* const* d_in, const int* in_sizes, int n_in,
                              void* d_out, int out_size)
{
    const float* query = (const float*)d_in[0];
    const float* key_t = (const float*)d_in[1];
    const float* value = (const float*)d_in[2];
    const float* Wq    = (const float*)d_in[3];
    const float* bq    = (const float*)d_in[4];
    const float* Wk    = (const float*)d_in[5];
    const float* bk    = (const float*)d_in[6];
    const float* Wv    = (const float*)d_in[7];
    const float* bv    = (const float*)d_in[8];
    const float* Wo    = (const float*)d_in[9];
    const float* bo    = (const float*)d_in[10];
    const float* gamma = (const float*)d_in[11];
    const float* beta  = (const float*)d_in[12];

    float* out = (float*)d_out;
    const long long BSD = (long long)Bb * Ss * Dd;
    const long long ATT = (long long)Bb * Hh * Ss * (long long)Ss;

    float* attn_ext = out;
    int use_scratch = 1;
    float* out_ext = out;
    int out_internal = 0;
    if ((long long)out_size >= BSD + ATT) {
        attn_ext = out + BSD;
        use_scratch = 0;
    } else if ((long long)out_size == ATT) {
        attn_ext = out;
        use_scratch = 0;
        out_internal = 1;
    }

    cudaFuncSetAttribute(attn_mma_kernel,
                         cudaFuncAttributeMaxDynamicSharedMemorySize, ATTN_SMEM);
    cudaFuncSetAttribute(gemm_f16_kernel,
                         cudaFuncAttributeMaxDynamicSharedMemorySize, GFSMEM);

    prep_w_kernel<<<dim3(1024, 4), 256>>>(Wq, Wk, Wv, Wo);
    prep_i_kernel<<<dim3(8192, 3), 256>>>(query, key_t, value);

    dim3 ggrid(Dd / BN, Mtot / BM);         // (8, 64)
    dim3 ggrid3(Dd / BN, Mtot / BM, 3);     // QKV fused
    gemm_f16_kernel<<<ggrid3, 256, GFSMEM>>>(bq, bk, bv, 0);

    vtrans_kernel<<<dim3(Ss / 64, Bb * Hh), 256>>>();

    attn_mma_kernel<<<dim3(Ss / 128, Bb * Hh), 256, ATTN_SMEM>>>(attn_ext, use_scratch);

    gemm_f16_kernel<<<ggrid, 256, GFSMEM>>>(nullptr, nullptr, nullptr, 1);

    ln_kernel<<<Mtot, 256>>>(gamma, beta, bo, query, out_ext, out_internal);
}